// round 14
// baseline (speedup 1.0000x reference)
#include <cuda_runtime.h>
#include <cstdint>

#define NN 50000
#define NE 800000
#define F  64
#define NLAYERS 3
#define NCHUNKS 196     // ceil(NN/256)

#define TE  128         // edges per block in edge kernel
#define PAD 68          // h1s/h2n row pad in floats (272B, 16B-aligned)
#define WST 160         // W2p row stride in floats (cg*20 swizzle, 16B-aligned)

// ---------------- scratch (device globals; no allocation allowed) ----------
__device__ float g_u [NN * F];
__device__ float g_v [NN * F];
__device__ float g_x1[NN * F];
__device__ float g_x2[NN * F];
__device__ int   g_cnt [NN];
__device__ int   g_part[NN];
__device__ int   g_run [NN];
__device__ int   g_bsum[256];
__device__ int   g_ssrc[NE];
__device__ int   g_sdst[NE];

// ===========================================================================
// Prep: counting sort of edges by dst (once per launch)
// ===========================================================================
__global__ __launch_bounds__(256) void hist_kernel(const int* __restrict__ ei,
                                                   int* __restrict__ cnt)
{
    int e = blockIdx.x * 256 + threadIdx.x;
    atomicAdd(&cnt[ei[NE + e]], 1);
}

__device__ __forceinline__ int block_scan_excl(int v, int t, int* wsum)
{
    int lane = t & 31, w = t >> 5;
    int s = v;
    #pragma unroll
    for (int d = 1; d < 32; d <<= 1) {
        int n = __shfl_up_sync(0xffffffffu, s, d);
        if (lane >= d) s += n;
    }
    if (lane == 31) wsum[w] = s;
    __syncthreads();
    if (w == 0) {
        int ws = (lane < 8) ? wsum[lane] : 0;
        #pragma unroll
        for (int d = 1; d < 8; d <<= 1) {
            int n = __shfl_up_sync(0xffffffffu, ws, d);
            if (lane >= d) ws += n;
        }
        if (lane < 8) wsum[lane] = ws;
    }
    __syncthreads();
    int base = (w > 0) ? wsum[w - 1] : 0;
    return s - v + base;
}

__global__ __launch_bounds__(256) void scan1_kernel(const int* __restrict__ cnt,
                                                    int* __restrict__ part,
                                                    int* __restrict__ bsum)
{
    __shared__ int wsum[8];
    int t = threadIdx.x;
    int i = blockIdx.x * 256 + t;
    int v = (i < NN) ? cnt[i] : 0;
    int ex = block_scan_excl(v, t, wsum);
    if (i < NN) part[i] = ex;
    if (t == 255) bsum[blockIdx.x] = ex + v;
}

__global__ __launch_bounds__(256) void scan23_kernel(const int* __restrict__ part,
                                                     const int* __restrict__ bsum,
                                                     int* __restrict__ run)
{
    __shared__ int wsum[8];
    __shared__ int sb[256];
    int t = threadIdx.x;
    int v = (t < NCHUNKS) ? bsum[t] : 0;
    int ex = block_scan_excl(v, t, wsum);
    sb[t] = ex;
    __syncthreads();
    #pragma unroll 4
    for (int i = t; i < NN; i += 256)
        run[i] = part[i] + sb[i >> 8];
}

__global__ __launch_bounds__(256) void scatter_kernel(const int* __restrict__ ei,
                                                      int* __restrict__ run,
                                                      int* __restrict__ ssrc,
                                                      int* __restrict__ sdst)
{
    int e = blockIdx.x * 256 + threadIdx.x;
    int s = ei[e];
    int d = ei[NE + e];
    int pos = atomicAdd(&run[d], 1);
    ssrc[pos] = s;
    sdst[pos] = d;
}

// ===========================================================================
// Node kernel: u = x@(W1a - W1b) + b1 ;  v = x@W1b  (proven R7/R10 version)
// Also zero-fills a slice of this layer's output buffer y.
// ===========================================================================
__global__ __launch_bounds__(256) void node_kernel(
    const float* __restrict__ x,
    const float* __restrict__ W1,   // [128,64]
    const float* __restrict__ b1g,  // [64]
    float* __restrict__ u,
    float* __restrict__ v,
    float* __restrict__ y)
{
    __shared__ float W1s[128 * 64];
    __shared__ float xs[32 * 64];

    const int t  = threadIdx.x;
    const int n0 = blockIdx.x * 32;

    {
        int base = blockIdx.x * 2048 + t * 8;
        if (base < NN * F) {
            float4 z = make_float4(0.f, 0.f, 0.f, 0.f);
            *(float4*)(y + base)     = z;
            *(float4*)(y + base + 4) = z;
        }
    }

    #pragma unroll
    for (int r = 0; r < 32; r++) W1s[r * 256 + t] = W1[r * 256 + t];

    #pragma unroll
    for (int r = 0; r < 8; r++) {
        int idx  = r * 256 + t;
        int nn   = idx >> 6;
        int f    = idx & 63;
        int node = n0 + nn;
        xs[idx] = (node < NN) ? x[node * F + f] : 0.f;
    }
    __syncthreads();

    const int jc = (t & 31) * 2;
    const int ng = t >> 5;

    unsigned long long accA[4], accC[4];
    #pragma unroll
    for (int s = 0; s < 4; s++) { accA[s] = 0ull; accC[s] = 0ull; }

    #pragma unroll 8
    for (int k = 0; k < F; k++) {
        unsigned long long wa = *(const unsigned long long*)&W1s[k * F + jc];
        unsigned long long wb = *(const unsigned long long*)&W1s[(F + k) * F + jc];
        #pragma unroll
        for (int s = 0; s < 4; s++) {
            float xk = xs[(ng + 8 * s) * F + k];
            unsigned long long hh;
            unsigned hb = __float_as_uint(xk);
            asm("mov.b64 %0, {%1, %1};" : "=l"(hh) : "r"(hb));
            asm("fma.rn.f32x2 %0, %1, %2, %0;" : "+l"(accA[s]) : "l"(hh), "l"(wa));
            asm("fma.rn.f32x2 %0, %1, %2, %0;" : "+l"(accC[s]) : "l"(hh), "l"(wb));
        }
    }

    const float bb0 = b1g[jc], bb1 = b1g[jc + 1];
    #pragma unroll
    for (int s = 0; s < 4; s++) {
        int node = n0 + ng + 8 * s;
        if (node < NN) {
            unsigned a0u, a1u, c0u, c1u;
            asm("mov.b64 {%0, %1}, %2;" : "=r"(a0u), "=r"(a1u) : "l"(accA[s]));
            asm("mov.b64 {%0, %1}, %2;" : "=r"(c0u), "=r"(c1u) : "l"(accC[s]));
            float a0 = __uint_as_float(a0u), a1 = __uint_as_float(a1u);
            float c0 = __uint_as_float(c0u), c1 = __uint_as_float(c1u);
            u[node * F + jc]     = a0 - c0 + bb0;
            u[node * F + jc + 1] = a1 - c1 + bb1;
            v[node * F + jc]     = c0;
            v[node * F + jc + 1] = c1;
        }
    }
}

// ===========================================================================
// Edge kernel (dst-sorted, TE=128 edges/block, 256 threads):
//  phase1: h1s[e][k] = relu(u[dst]+v[src])  row-major, coalesced (proven)
//  phase2: k-pair packed f32x2, tile 4 edges x 8 COLS (acc 32 ull):
//          per warp-k2: 8 crossbar cyc vs 16 fma cyc -> fma-bound, 2x headroom
//          W2p layout: row k2, col group cg at offset cg*20 (all-32-bank tile)
//  phase3: h2 -> overlaid smem, serial segmented max, 1 atomic per segment.
// ===========================================================================
__global__ __launch_bounds__(256) void edge_kernel(
    const int* __restrict__ ssrc,
    const int* __restrict__ sdst,
    const float* __restrict__ u,
    const float* __restrict__ v,
    const float* __restrict__ W2,       // [64,64]
    const float* __restrict__ b2g,      // [64]
    float* __restrict__ out)
{
    extern __shared__ float smem[];
    float* hbuf = smem;                       // TE*PAD (h1s, then h2n)
    float* W2p  = smem + TE * PAD;            // 32*WST k-pair interleaved, cg*20
    float* b2s  = W2p + 32 * WST;             // 64
    int*   si   = (int*)(b2s + 64);           // TE
    int*   di   = si + TE;                    // TE

    const int t  = threadIdx.x;
    const int e0 = blockIdx.x * TE;

    // stage W2: W2p[k2][ (c>>3)*20 + (c&7)*2 + p ] = W2[2*k2+p][c]
    #pragma unroll
    for (int r = 0; r < 4; r++) {
        int j  = r * 256 + t;          // 1024 float4 of W2
        int kk = j >> 4;               // row 0..63
        int c0 = (j & 15) * 4;         // col base
        float4 w4 = *(const float4*)(W2 + kk * 64 + c0);
        const float* wp = (const float*)&w4;
        int k2 = kk >> 1, p = kk & 1;
        #pragma unroll
        for (int i = 0; i < 4; i++) {
            int c = c0 + i;
            W2p[k2 * WST + (c >> 3) * 20 + (c & 7) * 2 + p] = wp[i];
        }
    }
    if (t < 64) b2s[t] = b2g[t];
    if (t < TE)            si[t]      = ssrc[e0 + t];
    else if (t < 2 * TE)   di[t - TE] = sdst[e0 + t - TE];
    __syncthreads();

    // phase 1: h1 = relu(u[dst] + v[src]) -> smem row-major (float4, coalesced)
    #pragma unroll 8
    for (int r = 0; r < 8; r++) {
        int idx = r * 256 + t;        // over 2048 float4 slots
        int e   = idx >> 4;           // edge 0..127
        int q   = idx & 15;           // float4 within row
        float4 uq = *(const float4*)(u + (size_t)di[e] * F + q * 4);
        float4 vq = *(const float4*)(v + (size_t)si[e] * F + q * 4);
        float4 h;
        h.x = fmaxf(uq.x + vq.x, 0.f);
        h.y = fmaxf(uq.y + vq.y, 0.f);
        h.z = fmaxf(uq.z + vq.z, 0.f);
        h.w = fmaxf(uq.w + vq.w, 0.f);
        *(float4*)&hbuf[e * PAD + q * 4] = h;
    }
    __syncthreads();

    // phase 2: tile = 4 edges x 8 cols, k-pair packed
    const int cg   = t & 7;     // col group: cols cg*8 .. +7
    const int eg   = t >> 3;    // edge group: edges eg*4 .. +3
    const int woff = cg * 20;

    unsigned long long acc[4][8];
    #pragma unroll
    for (int i = 0; i < 4; i++)
        #pragma unroll
        for (int c = 0; c < 8; c++)
            acc[i][c] = 0ull;

    const float* hrow = hbuf + eg * 4 * PAD;
    #pragma unroll 2
    for (int k2 = 0; k2 < 32; k2++) {
        unsigned long long hp[4];
        #pragma unroll
        for (int i = 0; i < 4; i++)
            hp[i] = *(const unsigned long long*)&hrow[i * PAD + 2 * k2];

        const float* wr = W2p + k2 * WST + woff;
        ulonglong2 wA = *(const ulonglong2*)wr;
        ulonglong2 wB = *(const ulonglong2*)(wr + 4);
        ulonglong2 wC = *(const ulonglong2*)(wr + 8);
        ulonglong2 wD = *(const ulonglong2*)(wr + 12);
        unsigned long long wv[8] = {wA.x, wA.y, wB.x, wB.y,
                                    wC.x, wC.y, wD.x, wD.y};

        #pragma unroll
        for (int i = 0; i < 4; i++)
            #pragma unroll
            for (int c = 0; c < 8; c++)
                asm("fma.rn.f32x2 %0, %1, %2, %0;"
                    : "+l"(acc[i][c]) : "l"(hp[i]), "l"(wv[c]));
    }

    // phase 3a: h2 = lo + hi + b2 -> overlaid smem h2n[e][PAD]
    __syncthreads();
    #pragma unroll
    for (int i = 0; i < 4; i++) {
        int e = eg * 4 + i;
        float4 o1, o2;
        float* p1 = (float*)&o1;
        float* p2 = (float*)&o2;
        #pragma unroll
        for (int c = 0; c < 4; c++) {
            unsigned lo, hi;
            asm("mov.b64 {%0, %1}, %2;" : "=r"(lo), "=r"(hi) : "l"(acc[i][c]));
            p1[c] = __uint_as_float(lo) + __uint_as_float(hi) + b2s[cg * 8 + c];
        }
        #pragma unroll
        for (int c = 0; c < 4; c++) {
            unsigned lo, hi;
            asm("mov.b64 {%0, %1}, %2;" : "=r"(lo), "=r"(hi) : "l"(acc[i][c + 4]));
            p2[c] = __uint_as_float(lo) + __uint_as_float(hi) + b2s[cg * 8 + 4 + c];
        }
        *(float4*)&hbuf[e * PAD + cg * 8]     = o1;
        *(float4*)&hbuf[e * PAD + cg * 8 + 4] = o2;
    }
    __syncthreads();

    // phase 3b: segmented max over dst; thread: col c, rows [g*32, g*32+32)
    {
        const int c  = t & 63;
        const int g  = t >> 6;      // 0..3
        const int r0 = g * 32;
        int   cur = di[r0];
        float m   = hbuf[r0 * PAD + c];
        #pragma unroll 1
        for (int r = r0 + 1; r < r0 + 32; r++) {
            int   d2  = di[r];
            float val = hbuf[r * PAD + c];
            if (d2 != cur) {
                atomicMax((unsigned*)out + (size_t)cur * F + c,
                          __float_as_uint(fmaxf(m, 0.f)));
                cur = d2;
                m   = val;
            } else {
                m = fmaxf(m, val);
            }
        }
        atomicMax((unsigned*)out + (size_t)cur * F + c,
                  __float_as_uint(fmaxf(m, 0.f)));
    }
}

// ===========================================================================
// launch
// ===========================================================================
extern "C" void kernel_launch(void* const* d_in, const int* in_sizes, int n_in,
                              void* d_out, int out_size)
{
    const float* x   = (const float*)d_in[0];
    const int*   ei  = (const int*)d_in[1];
    const float* W1  = (const float*)d_in[2];
    const float* b1  = (const float*)d_in[3];
    const float* W2  = (const float*)d_in[4];
    const float* b2  = (const float*)d_in[5];
    float* out = (float*)d_out;

    float *u, *v, *x1, *x2;
    int *cnt, *part, *run, *bsum, *ssrc, *sdst;
    cudaGetSymbolAddress((void**)&u,    g_u);
    cudaGetSymbolAddress((void**)&v,    g_v);
    cudaGetSymbolAddress((void**)&x1,   g_x1);
    cudaGetSymbolAddress((void**)&x2,   g_x2);
    cudaGetSymbolAddress((void**)&cnt,  g_cnt);
    cudaGetSymbolAddress((void**)&part, g_part);
    cudaGetSymbolAddress((void**)&run,  g_run);
    cudaGetSymbolAddress((void**)&bsum, g_bsum);
    cudaGetSymbolAddress((void**)&ssrc, g_ssrc);
    cudaGetSymbolAddress((void**)&sdst, g_sdst);

    // smem: hbuf 128*68*4=34816 ; W2p 32*160*4=20480 ; b2 256 ; si/di 1024
    const int smem_bytes = TE * PAD * 4 + 32 * WST * 4 + 64 * 4 + 2 * TE * 4;
    cudaFuncSetAttribute(edge_kernel, cudaFuncAttributeMaxDynamicSharedMemorySize,
                         smem_bytes);

    const int node_blocks = (NN + 31) / 32;       // 1563
    const int edge_blocks = NE / TE;              // 6250
    const int eth_blocks  = NE / 256;             // 3125

    cudaMemsetAsync(cnt, 0, NN * sizeof(int));
    hist_kernel<<<eth_blocks, 256>>>(ei, cnt);
    scan1_kernel<<<NCHUNKS, 256>>>(cnt, part, bsum);
    scan23_kernel<<<1, 256>>>(part, bsum, run);

    const float* cur = x;
    float* bufs[NLAYERS] = {x1, x2, out};

    for (int l = 0; l < NLAYERS; l++) {
        float* y = bufs[l];
        node_kernel<<<node_blocks, 256>>>(cur, W1 + l * 128 * 64, b1 + l * 64,
                                          u, v, y);
        if (l == 0)
            scatter_kernel<<<eth_blocks, 256>>>(ei, run, ssrc, sdst);
        edge_kernel<<<edge_blocks, 256, smem_bytes>>>(ssrc, sdst, u, v,
                                                      W2 + l * 64 * 64,
                                                      b2 + l * 64, y);
        cur = y;
    }
}

// round 15
// speedup vs baseline: 1.1068x; 1.1068x over previous
#include <cuda_runtime.h>

#define NN 50000
#define NE 800000
#define F  64
#define NLAYERS 3

#define TE  64          // edges per block in edge kernel
#define PAD 68          // h1s/h2n row pad in floats (272B, 16B-aligned)
#define WST 144         // W2p row stride in floats (swizzled, 576B = 36x16B)

// ---------------- scratch (device globals; no allocation allowed) ----------
__device__ float g_u [NN * F];
__device__ float g_v [NN * F];
__device__ float g_x1[NN * F];
__device__ float g_x2[NN * F];
__device__ int   g_cnt [NN];
__device__ int   g_part[NN];
__device__ int   g_run [NN];
__device__ int   g_bsum[256];
__device__ int   g_ssrc[NE];
__device__ int   g_sdst[NE];

// ===========================================================================
// Prep: counting sort of edges by dst (once per launch)
// ===========================================================================
__global__ __launch_bounds__(256) void zero_int_kernel(int* __restrict__ p)
{
    int i = blockIdx.x * 256 + threadIdx.x;
    if (i < NN) p[i] = 0;
}

__global__ __launch_bounds__(256) void hist_kernel(const int* __restrict__ ei,
                                                   int* __restrict__ cnt)
{
    int e = blockIdx.x * 256 + threadIdx.x;
    atomicAdd(&cnt[ei[NE + e]], 1);
}

__device__ __forceinline__ int block_scan_excl(int v, int t, int* wsum)
{
    int lane = t & 31, w = t >> 5;
    int s = v;
    #pragma unroll
    for (int d = 1; d < 32; d <<= 1) {
        int n = __shfl_up_sync(0xffffffffu, s, d);
        if (lane >= d) s += n;
    }
    if (lane == 31) wsum[w] = s;
    __syncthreads();
    if (w == 0) {
        int ws = (lane < 8) ? wsum[lane] : 0;
        #pragma unroll
        for (int d = 1; d < 8; d <<= 1) {
            int n = __shfl_up_sync(0xffffffffu, ws, d);
            if (lane >= d) ws += n;
        }
        if (lane < 8) wsum[lane] = ws;
    }
    __syncthreads();
    int base = (w > 0) ? wsum[w - 1] : 0;
    return s - v + base;
}

__global__ __launch_bounds__(256) void scan1_kernel(const int* __restrict__ cnt,
                                                    int* __restrict__ part,
                                                    int* __restrict__ bsum)
{
    __shared__ int wsum[8];
    int t = threadIdx.x;
    int i = blockIdx.x * 256 + t;
    int v = (i < NN) ? cnt[i] : 0;
    int ex = block_scan_excl(v, t, wsum);
    if (i < NN) part[i] = ex;
    if (t == 255) bsum[blockIdx.x] = ex + v;
}

__global__ __launch_bounds__(256) void scan2_kernel(int* __restrict__ bsum, int n)
{
    __shared__ int wsum[8];
    int t = threadIdx.x;
    int v = (t < n) ? bsum[t] : 0;
    int ex = block_scan_excl(v, t, wsum);
    if (t < n) bsum[t] = ex;
}

__global__ __launch_bounds__(256) void scan3_kernel(const int* __restrict__ part,
                                                    const int* __restrict__ bsum,
                                                    int* __restrict__ run)
{
    int i = blockIdx.x * 256 + threadIdx.x;
    if (i < NN) run[i] = part[i] + bsum[blockIdx.x];
}

__global__ __launch_bounds__(256) void scatter_kernel(const int* __restrict__ ei,
                                                      int* __restrict__ run,
                                                      int* __restrict__ ssrc,
                                                      int* __restrict__ sdst)
{
    int e = blockIdx.x * 256 + threadIdx.x;
    int s = ei[e];
    int d = ei[NE + e];
    int pos = atomicAdd(&run[d], 1);
    ssrc[pos] = s;
    sdst[pos] = d;
}

// ===========================================================================
// Node kernel: u = x@(W1a - W1b) + b1 ;  v = x@W1b  (packed f32x2)
// Also zero-fills a slice of this layer's output buffer y.
// ===========================================================================
__global__ __launch_bounds__(256) void node_kernel(
    const float* __restrict__ x,
    const float* __restrict__ W1,   // [128,64]
    const float* __restrict__ b1g,  // [64]
    float* __restrict__ u,
    float* __restrict__ v,
    float* __restrict__ y)
{
    __shared__ float W1s[128 * 64];
    __shared__ float xs[32 * 64];

    const int t  = threadIdx.x;
    const int n0 = blockIdx.x * 32;

    {
        int base = blockIdx.x * 2048 + t * 8;
        if (base < NN * F) {
            float4 z = make_float4(0.f, 0.f, 0.f, 0.f);
            *(float4*)(y + base)     = z;
            *(float4*)(y + base + 4) = z;
        }
    }

    #pragma unroll
    for (int r = 0; r < 32; r++) W1s[r * 256 + t] = W1[r * 256 + t];

    #pragma unroll
    for (int r = 0; r < 8; r++) {
        int idx  = r * 256 + t;
        int nn   = idx >> 6;
        int f    = idx & 63;
        int node = n0 + nn;
        xs[idx] = (node < NN) ? x[node * F + f] : 0.f;
    }
    __syncthreads();

    const int jc = (t & 31) * 2;
    const int ng = t >> 5;

    unsigned long long accA[4], accC[4];
    #pragma unroll
    for (int s = 0; s < 4; s++) { accA[s] = 0ull; accC[s] = 0ull; }

    #pragma unroll 8
    for (int k = 0; k < F; k++) {
        unsigned long long wa = *(const unsigned long long*)&W1s[k * F + jc];
        unsigned long long wb = *(const unsigned long long*)&W1s[(F + k) * F + jc];
        #pragma unroll
        for (int s = 0; s < 4; s++) {
            float xk = xs[(ng + 8 * s) * F + k];
            unsigned long long hh;
            unsigned hb = __float_as_uint(xk);
            asm("mov.b64 %0, {%1, %1};" : "=l"(hh) : "r"(hb));
            asm("fma.rn.f32x2 %0, %1, %2, %0;" : "+l"(accA[s]) : "l"(hh), "l"(wa));
            asm("fma.rn.f32x2 %0, %1, %2, %0;" : "+l"(accC[s]) : "l"(hh), "l"(wb));
        }
    }

    const float bb0 = b1g[jc], bb1 = b1g[jc + 1];
    #pragma unroll
    for (int s = 0; s < 4; s++) {
        int node = n0 + ng + 8 * s;
        if (node < NN) {
            unsigned a0u, a1u, c0u, c1u;
            asm("mov.b64 {%0, %1}, %2;" : "=r"(a0u), "=r"(a1u) : "l"(accA[s]));
            asm("mov.b64 {%0, %1}, %2;" : "=r"(c0u), "=r"(c1u) : "l"(accC[s]));
            float a0 = __uint_as_float(a0u), a1 = __uint_as_float(a1u);
            float c0 = __uint_as_float(c0u), c1 = __uint_as_float(c1u);
            u[node * F + jc]     = a0 - c0 + bb0;
            u[node * F + jc + 1] = a1 - c1 + bb1;
            v[node * F + jc]     = c0;
            v[node * F + jc + 1] = c1;
        }
    }
}

// ===========================================================================
// Edge kernel (dst-sorted, TE=64 edges/block, 256 threads):
//  phase1: h1s[e][k] = relu(u[dst]+v[src])  row-major, coalesced (R3-proven)
//  phase2: K-PAIR packed f32x2, tile 4 edges x 4 cols, acc = 32 regs.
//          2 k-pairs per iter: h via one LDS.128 per edge (contiguous k),
//          W2 staged k-pair-interleaved + BANK-SWIZZLED -> conflict-free.
//  phase3: h2 -> overlaid smem, serial segmented max, 1 atomic per segment.
// ===========================================================================
__global__ __launch_bounds__(256) void edge_kernel(
    const int* __restrict__ ssrc,
    const int* __restrict__ sdst,
    const float* __restrict__ u,
    const float* __restrict__ v,
    const float* __restrict__ W2,       // [64,64]
    const float* __restrict__ b2g,      // [64]
    float* __restrict__ out)
{
    extern __shared__ float smem[];
    float* hbuf = smem;                       // TE*PAD floats (h1s, then h2n)
    float* W2p  = smem + TE * PAD;            // 32*WST  k-pair-interleaved+swizzled
    float* b2s  = W2p + 32 * WST;             // 64
    int*   si   = (int*)(b2s + 64);           // TE
    int*   di   = si + TE;                    // TE

    const int t  = threadIdx.x;
    const int e0 = blockIdx.x * TE;

    // stage W2: W2p[k2][swizzle(c) + p] = W2[2*k2+p][c]
    // swizzle: cg = c>>2, off = cg*8 + (cg>>2)*4 + (c&3)*2  (conflict-free loads)
    #pragma unroll
    for (int r = 0; r < 4; r++) {
        int j  = r * 256 + t;          // float4 index over W2 (1024 total)
        int kk = j >> 4;               // row 0..63
        int c0 = (j & 15) * 4;         // col base
        float4 w4 = *(const float4*)(W2 + kk * 64 + c0);
        int k2 = kk >> 1, p = kk & 1;
        int cg = c0 >> 2;
        int base = k2 * WST + cg * 8 + (cg >> 2) * 4 + p;
        W2p[base]     = w4.x;
        W2p[base + 2] = w4.y;
        W2p[base + 4] = w4.z;
        W2p[base + 6] = w4.w;
    }
    if (t < 64) b2s[t] = b2g[t];
    if (t < TE)            si[t]      = ssrc[e0 + t];
    else if (t < 2 * TE)   di[t - TE] = sdst[e0 + t - TE];
    __syncthreads();

    // phase 1: h1 = relu(u[dst] + v[src]) -> smem row-major (float4, coalesced)
    #pragma unroll 4
    for (int r = 0; r < 4; r++) {
        int idx = r * 256 + t;        // over 1024 float4 slots
        int e   = idx >> 4;           // edge 0..63
        int q   = idx & 15;           // float4 within row
        float4 uq = *(const float4*)(u + (size_t)di[e] * F + q * 4);
        float4 vq = *(const float4*)(v + (size_t)si[e] * F + q * 4);
        float4 h;
        h.x = fmaxf(uq.x + vq.x, 0.f);
        h.y = fmaxf(uq.y + vq.y, 0.f);
        h.z = fmaxf(uq.z + vq.z, 0.f);
        h.w = fmaxf(uq.w + vq.w, 0.f);
        *(float4*)&hbuf[e * PAD + q * 4] = h;
    }
    __syncthreads();

    // phase 2: tile = 4 edges x 4 cols, k-pair packed, 2 k-pairs per iter
    const int cg   = t & 15;    // col group: cols cg*4 .. +3
    const int eg   = t >> 4;    // edge group: edges eg*4 .. +3
    const int woff = cg * 8 + (cg >> 2) * 4;

    unsigned long long acc[4][4];
    #pragma unroll
    for (int i = 0; i < 4; i++)
        #pragma unroll
        for (int c = 0; c < 4; c++)
            acc[i][c] = 0ull;

    #pragma unroll 8
    for (int kq = 0; kq < 16; kq++) {       // kq covers k2 = 2kq, 2kq+1
        ulonglong2 hq[4];
        #pragma unroll
        for (int i = 0; i < 4; i++)
            hq[i] = *(const ulonglong2*)&hbuf[(eg * 4 + i) * PAD + 4 * kq];

        const float* wr0 = W2p + (2 * kq) * WST + woff;
        const float* wr1 = wr0 + WST;
        ulonglong2 wa01 = *(const ulonglong2*)wr0;
        ulonglong2 wa23 = *(const ulonglong2*)(wr0 + 4);
        ulonglong2 wb01 = *(const ulonglong2*)wr1;
        ulonglong2 wb23 = *(const ulonglong2*)(wr1 + 4);
        unsigned long long wva[4] = {wa01.x, wa01.y, wa23.x, wa23.y};
        unsigned long long wvb[4] = {wb01.x, wb01.y, wb23.x, wb23.y};

        #pragma unroll
        for (int i = 0; i < 4; i++) {
            #pragma unroll
            for (int c = 0; c < 4; c++) {
                asm("fma.rn.f32x2 %0, %1, %2, %0;"
                    : "+l"(acc[i][c]) : "l"(hq[i].x), "l"(wva[c]));
                asm("fma.rn.f32x2 %0, %1, %2, %0;"
                    : "+l"(acc[i][c]) : "l"(hq[i].y), "l"(wvb[c]));
            }
        }
    }

    // phase 3a: h2 = lo + hi + b2 -> overlaid smem h2n[e][PAD]
    __syncthreads();
    #pragma unroll
    for (int i = 0; i < 4; i++) {
        int e = eg * 4 + i;
        float4 o;
        float* op = (float*)&o;
        #pragma unroll
        for (int c = 0; c < 4; c++) {
            unsigned lo, hi;
            asm("mov.b64 {%0, %1}, %2;" : "=r"(lo), "=r"(hi) : "l"(acc[i][c]));
            op[c] = __uint_as_float(lo) + __uint_as_float(hi) + b2s[cg * 4 + c];
        }
        *(float4*)&hbuf[e * PAD + cg * 4] = o;
    }
    __syncthreads();

    // phase 3b: segmented max over dst; thread: col c, rows [g*16, g*16+16)
    {
        const int c  = t & 63;
        const int g  = t >> 6;      // 0..3
        const int r0 = g * 16;
        int   cur = di[r0];
        float m   = hbuf[r0 * PAD + c];
        #pragma unroll 1
        for (int r = r0 + 1; r < r0 + 16; r++) {
            int   d2  = di[r];
            float val = hbuf[r * PAD + c];
            if (d2 != cur) {
                atomicMax((unsigned*)out + (size_t)cur * F + c,
                          __float_as_uint(fmaxf(m, 0.f)));
                cur = d2;
                m   = val;
            } else {
                m = fmaxf(m, val);
            }
        }
        atomicMax((unsigned*)out + (size_t)cur * F + c,
                  __float_as_uint(fmaxf(m, 0.f)));
    }
}

// ===========================================================================
// launch
// ===========================================================================
extern "C" void kernel_launch(void* const* d_in, const int* in_sizes, int n_in,
                              void* d_out, int out_size)
{
    const float* x   = (const float*)d_in[0];
    const int*   ei  = (const int*)d_in[1];
    const float* W1  = (const float*)d_in[2];
    const float* b1  = (const float*)d_in[3];
    const float* W2  = (const float*)d_in[4];
    const float* b2  = (const float*)d_in[5];
    float* out = (float*)d_out;

    float *u, *v, *x1, *x2;
    int *cnt, *part, *run, *bsum, *ssrc, *sdst;
    cudaGetSymbolAddress((void**)&u,    g_u);
    cudaGetSymbolAddress((void**)&v,    g_v);
    cudaGetSymbolAddress((void**)&x1,   g_x1);
    cudaGetSymbolAddress((void**)&x2,   g_x2);
    cudaGetSymbolAddress((void**)&cnt,  g_cnt);
    cudaGetSymbolAddress((void**)&part, g_part);
    cudaGetSymbolAddress((void**)&run,  g_run);
    cudaGetSymbolAddress((void**)&bsum, g_bsum);
    cudaGetSymbolAddress((void**)&ssrc, g_ssrc);
    cudaGetSymbolAddress((void**)&sdst, g_sdst);

    // smem: hbuf 64*68*4=17408 ; W2p 32*144*4=18432 ; b2 256 ; si/di 512
    const int smem_bytes = TE * PAD * 4 + 32 * WST * 4 + 64 * 4 + 2 * TE * 4;
    cudaFuncSetAttribute(edge_kernel, cudaFuncAttributeMaxDynamicSharedMemorySize,
                         smem_bytes);

    const int nchunks     = (NN + 255) / 256;     // 196
    const int node_blocks = (NN + 31) / 32;       // 1563
    const int edge_blocks = NE / TE;              // 12500
    const int eth_blocks  = NE / 256;             // 3125

    zero_int_kernel<<<nchunks, 256>>>(cnt);
    hist_kernel<<<eth_blocks, 256>>>(ei, cnt);
    scan1_kernel<<<nchunks, 256>>>(cnt, part, bsum);
    scan2_kernel<<<1, 256>>>(bsum, nchunks);
    scan3_kernel<<<nchunks, 256>>>(part, bsum, run);
    scatter_kernel<<<eth_blocks, 256>>>(ei, run, ssrc, sdst);

    const float* cur = x;
    float* bufs[NLAYERS] = {x1, x2, out};

    for (int l = 0; l < NLAYERS; l++) {
        float* y = bufs[l];
        node_kernel<<<node_blocks, 256>>>(cur, W1 + l * 128 * 64, b1 + l * 64,
                                          u, v, y);
        edge_kernel<<<edge_blocks, 256, smem_bytes>>>(ssrc, sdst, u, v,
                                                      W2 + l * 64 * 64,
                                                      b2 + l * 64, y);
        cur = y;
    }
}